// round 1
// baseline (speedup 1.0000x reference)
#include <cuda_runtime.h>
#include <math_constants.h>
#include <cstdint>
#include <cstddef>

#define T_DIM 2048
#define E_DIM 1024
#define M_DIM 32768
#define H_DIM 16
#define D_DIM 64

// ---------------- device scratch (no allocations allowed) ----------------
__device__ float g_qkv[T_DIM * 3 * E_DIM];           // 24 MB  [T, 3E]
__device__ float g_y[T_DIM * E_DIM];                 // 8 MB   [T, E] attention out
__device__ float g_S[(size_t)T_DIM * M_DIM];         // 256 MB [T, M] mem scores
__device__ float g_mknorm[M_DIM];                    // |mem_key|^2
__device__ int   g_idx[T_DIM * 3];                   // top-3 indices
__device__ float g_comb[T_DIM * E_DIM];              // 8 MB combined

// ---------------- SGEMM: C[M,N] = A[M,K] * B[N,K]^T (NT), optional bias ----
// BIASED: C = -2*acc + bias[n]
template <int BIASED>
__global__ void __launch_bounds__(256)
sgemm_nt(const float* __restrict__ A, int lda,
         const float* __restrict__ B, int ldb,
         float* __restrict__ C, int ldc,
         int K, const float* __restrict__ bias) {
    __shared__ float As[8][132];
    __shared__ float Bs[8][132];
    const int tid = threadIdx.x;
    const int mBase = blockIdx.y * 128;
    const int nBase = blockIdx.x * 128;
    const int lr = tid >> 1;            // 0..127
    const int lc = (tid & 1) << 2;      // 0 or 4
    const float* Ag = A + (size_t)(mBase + lr) * lda + lc;
    const float* Bg = B + (size_t)(nBase + lr) * ldb + lc;
    const int tm = tid >> 4;            // 0..15
    const int tn = tid & 15;            // 0..15

    float acc[8][8];
#pragma unroll
    for (int i = 0; i < 8; i++)
#pragma unroll
        for (int j = 0; j < 8; j++) acc[i][j] = 0.0f;

    for (int k0 = 0; k0 < K; k0 += 8) {
        float4 av = *(const float4*)(Ag + k0);
        float4 bv = *(const float4*)(Bg + k0);
        __syncthreads();
        As[lc + 0][lr] = av.x; As[lc + 1][lr] = av.y;
        As[lc + 2][lr] = av.z; As[lc + 3][lr] = av.w;
        Bs[lc + 0][lr] = bv.x; Bs[lc + 1][lr] = bv.y;
        Bs[lc + 2][lr] = bv.z; Bs[lc + 3][lr] = bv.w;
        __syncthreads();
#pragma unroll
        for (int kk = 0; kk < 8; kk++) {
            float a[8], b[8];
            *(float4*)&a[0] = *(const float4*)&As[kk][tm * 8];
            *(float4*)&a[4] = *(const float4*)&As[kk][tm * 8 + 4];
            *(float4*)&b[0] = *(const float4*)&Bs[kk][tn * 8];
            *(float4*)&b[4] = *(const float4*)&Bs[kk][tn * 8 + 4];
#pragma unroll
            for (int i = 0; i < 8; i++)
#pragma unroll
                for (int j = 0; j < 8; j++)
                    acc[i][j] += a[i] * b[j];
        }
    }

#pragma unroll
    for (int i = 0; i < 8; i++) {
        size_t roff = (size_t)(mBase + tm * 8 + i) * ldc + nBase + tn * 8;
#pragma unroll
        for (int j = 0; j < 8; j += 4) {
            float4 v;
            v.x = acc[i][j]; v.y = acc[i][j + 1];
            v.z = acc[i][j + 2]; v.w = acc[i][j + 3];
            if (BIASED) {
                int c = nBase + tn * 8 + j;
                v.x = -2.0f * v.x + bias[c];
                v.y = -2.0f * v.y + bias[c + 1];
                v.z = -2.0f * v.z + bias[c + 2];
                v.w = -2.0f * v.w + bias[c + 3];
            }
            *(float4*)&C[roff + j] = v;
        }
    }
}

// ---------------- mem-key squared norms: one warp per key ----------------
__global__ void mknorm_kernel(const float* __restrict__ mem_db) {
    int m = blockIdx.x * (blockDim.x >> 5) + (threadIdx.x >> 5);
    int lane = threadIdx.x & 31;
    if (m >= M_DIM) return;
    const float* row = mem_db + (size_t)m * 2 * E_DIM;  // key part
    float s = 0.0f;
    for (int e = lane; e < E_DIM; e += 32) {
        float v = row[e];
        s += v * v;
    }
#pragma unroll
    for (int o = 16; o; o >>= 1) s += __shfl_xor_sync(0xffffffffu, s, o);
    if (lane == 0) g_mknorm[m] = s;
}

// ---------------- causal flash attention, fp32 ----------------
// block = (q-tile of 64, head). 256 threads, 4x4 microtiles.
__global__ void __launch_bounds__(256)
flash_kernel(const float* __restrict__ qkv, float* __restrict__ y) {
    extern __shared__ float sm[];
    float* Qs = sm;                       // [64][64]
    float* Ks = Qs + 64 * 64;             // [64][68]
    float* Vs = Ks + 64 * 68;             // [64][68]
    float* Ss = Vs + 64 * 68;             // [64][64]
    float* m_s = Ss + 64 * 64;            // [64]
    float* l_s = m_s + 64;                // [64]
    float* corr_s = l_s + 64;             // [64]
    float* red = corr_s + 64;             // [64][4]

    const int h = blockIdx.y;
    const int qt = blockIdx.x;
    const int tid = threadIdx.x;
    const int qbase = qt * 64;
    const int LDQ = 3 * E_DIM;

#pragma unroll
    for (int it = 0; it < 4; it++) {
        int idx = tid + it * 256;
        int r = idx >> 4, c4 = (idx & 15) << 2;
        *(float4*)&Qs[r * 64 + c4] =
            *(const float4*)&qkv[(size_t)(qbase + r) * LDQ + h * 64 + c4];
    }
    if (tid < 64) { m_s[tid] = -CUDART_INF_F; l_s[tid] = 0.0f; }

    const int tm = tid >> 4, tn = tid & 15;
    const int q0 = tm * 4, n0 = tn * 4;
    float acc[4][4] = {};

    for (int kt = 0; kt <= qt; kt++) {
        const int kbase = kt * 64;
        __syncthreads();  // protect Ks/Vs/Ss reads of previous iteration
#pragma unroll
        for (int it = 0; it < 4; it++) {
            int idx = tid + it * 256;
            int r = idx >> 4, c4 = (idx & 15) << 2;
            size_t rowoff = (size_t)(kbase + r) * LDQ + h * 64 + c4;
            *(float4*)&Ks[r * 68 + c4] = *(const float4*)&qkv[rowoff + E_DIM];
            *(float4*)&Vs[r * 68 + c4] = *(const float4*)&qkv[rowoff + 2 * E_DIM];
        }
        __syncthreads();

        // phase A: S = Q K^T * 1/sqrt(D)
        float s[4][4] = {};
#pragma unroll 8
        for (int d = 0; d < 64; d++) {
            float a[4], b[4];
#pragma unroll
            for (int i = 0; i < 4; i++) a[i] = Qs[(q0 + i) * 64 + d];
#pragma unroll
            for (int j = 0; j < 4; j++) b[j] = Ks[(n0 + j) * 68 + d];
#pragma unroll
            for (int i = 0; i < 4; i++)
#pragma unroll
                for (int j = 0; j < 4; j++) s[i][j] += a[i] * b[j];
        }
        const bool diag = (kt == qt);
#pragma unroll
        for (int i = 0; i < 4; i++)
#pragma unroll
            for (int j = 0; j < 4; j++) {
                float v = s[i][j] * 0.125f;
                if (diag && (n0 + j) > (q0 + i)) v = -CUDART_INF_F;
                Ss[(q0 + i) * 64 + (n0 + j)] = v;
            }
        __syncthreads();

        // phase B: online softmax (4 threads per row)
        const int r = tid >> 2, p = tid & 3;
        float mx = -CUDART_INF_F;
#pragma unroll
        for (int c = 0; c < 16; c++) mx = fmaxf(mx, Ss[r * 64 + p * 16 + c]);
        red[r * 4 + p] = mx;
        __syncthreads();
        if (p == 0) {
            float mt = fmaxf(fmaxf(red[r * 4], red[r * 4 + 1]),
                             fmaxf(red[r * 4 + 2], red[r * 4 + 3]));
            float mold = m_s[r];
            float mnew = fmaxf(mold, mt);
            corr_s[r] = expf(mold - mnew);   // exp(-inf)=0 on first tile
            m_s[r] = mnew;
        }
        __syncthreads();
        float mnew = m_s[r];
        float ps = 0.0f;
#pragma unroll
        for (int c = 0; c < 16; c++) {
            float e = expf(Ss[r * 64 + p * 16 + c] - mnew);
            Ss[r * 64 + p * 16 + c] = e;
            ps += e;
        }
        red[r * 4 + p] = ps;
        __syncthreads();
        if (p == 0)
            l_s[r] = l_s[r] * corr_s[r] +
                     red[r * 4] + red[r * 4 + 1] + red[r * 4 + 2] + red[r * 4 + 3];

        // phase C: acc = acc*corr + P V
        float cr[4];
#pragma unroll
        for (int i = 0; i < 4; i++) cr[i] = corr_s[q0 + i];
#pragma unroll
        for (int i = 0; i < 4; i++)
#pragma unroll
            for (int j = 0; j < 4; j++) acc[i][j] *= cr[i];
#pragma unroll 8
        for (int kk = 0; kk < 64; kk++) {
            float pv[4], vv[4];
#pragma unroll
            for (int i = 0; i < 4; i++) pv[i] = Ss[(q0 + i) * 64 + kk];
#pragma unroll
            for (int j = 0; j < 4; j++) vv[j] = Vs[kk * 68 + n0 + j];
#pragma unroll
            for (int i = 0; i < 4; i++)
#pragma unroll
                for (int j = 0; j < 4; j++) acc[i][j] += pv[i] * vv[j];
        }
    }
    __syncthreads();  // l_s writes visible
    float linv[4];
#pragma unroll
    for (int i = 0; i < 4; i++) linv[i] = 1.0f / l_s[q0 + i];
#pragma unroll
    for (int i = 0; i < 4; i++)
#pragma unroll
        for (int j = 0; j < 4; j++)
            y[(size_t)(qbase + q0 + i) * E_DIM + h * 64 + n0 + j] =
                acc[i][j] * linv[i];
}

// ---------------- top-3 smallest (value, then index) per token -----------
__device__ __forceinline__ void top3_insert(float v, int i,
                                            float& v0, int& i0,
                                            float& v1, int& i1,
                                            float& v2, int& i2) {
    bool lt2 = (v < v2) || (v == v2 && i < i2);
    if (lt2) {
        bool lt1 = (v < v1) || (v == v1 && i < i1);
        if (lt1) {
            v2 = v1; i2 = i1;
            bool lt0 = (v < v0) || (v == v0 && i < i0);
            if (lt0) { v1 = v0; i1 = i0; v0 = v; i0 = i; }
            else     { v1 = v;  i1 = i; }
        } else { v2 = v; i2 = i; }
    }
}

__global__ void __launch_bounds__(256) top3_kernel(const float* __restrict__ S) {
    __shared__ float sv[256][3];
    __shared__ int   si[256][3];
    const int t = blockIdx.x;
    const int tid = threadIdx.x;
    const float* row = S + (size_t)t * M_DIM;
    float v0 = CUDART_INF_F, v1 = CUDART_INF_F, v2 = CUDART_INF_F;
    int i0 = 0x7fffffff, i1 = 0x7fffffff, i2 = 0x7fffffff;
    for (int j = tid; j < M_DIM; j += 256)
        top3_insert(row[j], j, v0, i0, v1, i1, v2, i2);
    sv[tid][0] = v0; sv[tid][1] = v1; sv[tid][2] = v2;
    si[tid][0] = i0; si[tid][1] = i1; si[tid][2] = i2;
    for (int s = 128; s > 0; s >>= 1) {
        __syncthreads();
        if (tid < s) {
#pragma unroll
            for (int k = 0; k < 3; k++)
                top3_insert(sv[tid + s][k], si[tid + s][k],
                            v0, i0, v1, i1, v2, i2);
            sv[tid][0] = v0; sv[tid][1] = v1; sv[tid][2] = v2;
            si[tid][0] = i0; si[tid][1] = i1; si[tid][2] = i2;
        }
    }
    if (tid == 0) {
        g_idx[t * 3 + 0] = i0;
        g_idx[t * 3 + 1] = i1;
        g_idx[t * 3 + 2] = i2;
    }
}

// ---------------- gather + 3-way mem softmax + gated combine -------------
// one warp per (t, h): 512 threads/block, block per token
__global__ void __launch_bounds__(512)
memattn_kernel(const float* __restrict__ qkv,
               const float* __restrict__ mem_db,
               const float* __restrict__ y,
               const float* __restrict__ gate) {
    const int t = blockIdx.x;
    const int h = threadIdx.x >> 5;
    const int lane = threadIdx.x & 31;
    int id0 = g_idx[t * 3 + 0];
    int id1 = g_idx[t * 3 + 1];
    int id2 = g_idx[t * 3 + 2];
    const int d0 = lane * 2;
    size_t qoff = (size_t)t * 3 * E_DIM + h * 64 + d0;
    float q0 = qkv[qoff], q1 = qkv[qoff + 1];

    const float* k0p = mem_db + (size_t)id0 * 2 * E_DIM + h * 64;
    const float* k1p = mem_db + (size_t)id1 * 2 * E_DIM + h * 64;
    const float* k2p = mem_db + (size_t)id2 * 2 * E_DIM + h * 64;
    float s0 = q0 * k0p[d0] + q1 * k0p[d0 + 1];
    float s1 = q0 * k1p[d0] + q1 * k1p[d0 + 1];
    float s2 = q0 * k2p[d0] + q1 * k2p[d0 + 1];
#pragma unroll
    for (int o = 16; o; o >>= 1) {
        s0 += __shfl_xor_sync(0xffffffffu, s0, o);
        s1 += __shfl_xor_sync(0xffffffffu, s1, o);
        s2 += __shfl_xor_sync(0xffffffffu, s2, o);
    }
    // scale_mem = E / H**(-0.5) = E * sqrt(H) = 4096
    s0 *= 4096.0f; s1 *= 4096.0f; s2 *= 4096.0f;
    float m = fmaxf(s0, fmaxf(s1, s2));
    float e0 = expf(s0 - m), e1 = expf(s1 - m), e2 = expf(s2 - m);
    float inv = 1.0f / (e0 + e1 + e2);
    e0 *= inv; e1 *= inv; e2 *= inv;

    const float* v0p = k0p + E_DIM;
    const float* v1p = k1p + E_DIM;
    const float* v2p = k2p + E_DIM;
    float o0 = e0 * v0p[d0] + e1 * v1p[d0] + e2 * v2p[d0];
    float o1 = e0 * v0p[d0 + 1] + e1 * v1p[d0 + 1] + e2 * v2p[d0 + 1];

    float g = gate[h];
    size_t off = (size_t)t * E_DIM + h * 64 + d0;
    g_comb[off]     = o0 * g + y[off] * (1.0f - g);
    g_comb[off + 1] = o1 * g + y[off + 1] * (1.0f - g);
}

// ---------------- launch ----------------
extern "C" void kernel_launch(void* const* d_in, const int* in_sizes, int n_in,
                              void* d_out, int out_size) {
    const float* x = nullptr;
    const float* mem_db = nullptr;
    const float* W_attn = nullptr;
    const float* W_proj = nullptr;
    const float* gate = nullptr;
    for (int i = 0; i < n_in; i++) {
        switch (in_sizes[i]) {
            case 2048 * 1024:       x      = (const float*)d_in[i]; break;
            case 32768 * 2048:      mem_db = (const float*)d_in[i]; break;
            case 3072 * 1024:       W_attn = (const float*)d_in[i]; break;
            case 1024 * 1024:       W_proj = (const float*)d_in[i]; break;
            case 16:                gate   = (const float*)d_in[i]; break;
            default: break;
        }
    }
    float* out = (float*)d_out;

    void *p_qkv, *p_y, *p_S, *p_comb;
    cudaGetSymbolAddress(&p_qkv, g_qkv);
    cudaGetSymbolAddress(&p_y, g_y);
    cudaGetSymbolAddress(&p_S, g_S);
    cudaGetSymbolAddress(&p_comb, g_comb);
    float* qkv = (float*)p_qkv;
    float* y = (float*)p_y;
    float* S = (float*)p_S;
    float* comb = (float*)p_comb;
    void* p_mkn; cudaGetSymbolAddress(&p_mkn, g_mknorm);
    float* mkn = (float*)p_mkn;

    const int FLASH_SMEM = (64 * 64 + 64 * 68 + 64 * 68 + 64 * 64 + 64 * 3 + 64 * 4) * 4;
    cudaFuncSetAttribute(flash_kernel,
                         cudaFuncAttributeMaxDynamicSharedMemorySize, FLASH_SMEM);

    // 1) qkv = x @ W_attn^T : [2048, 3072]
    sgemm_nt<0><<<dim3(3072 / 128, 2048 / 128), 256>>>(
        x, E_DIM, W_attn, E_DIM, qkv, 3 * E_DIM, E_DIM, nullptr);

    // 2) |mem_key|^2
    mknorm_kernel<<<M_DIM / 8, 256>>>(mem_db);

    // 3) causal attention -> y [T, E]
    flash_kernel<<<dim3(T_DIM / 64, H_DIM), 256, FLASH_SMEM>>>(qkv, y);

    // 4) S = -2 * q @ mem_keys^T + |mk|^2  (rank-equivalent to d2)
    sgemm_nt<1><<<dim3(M_DIM / 128, T_DIM / 128), 256>>>(
        qkv, 3 * E_DIM, mem_db, 2 * E_DIM, S, M_DIM, E_DIM, mkn);

    // 5) top-3 per token
    top3_kernel<<<T_DIM, 256>>>(S);

    // 6) mem attention + gated combine -> comb [T, E]
    memattn_kernel<<<T_DIM, 512>>>(qkv, mem_db, y, gate);

    // 7) out = comb @ W_proj^T
    sgemm_nt<0><<<dim3(1024 / 128, 2048 / 128), 256>>>(
        comb, E_DIM, W_proj, E_DIM, out, E_DIM, E_DIM, nullptr);
}

// round 3
// speedup vs baseline: 2.1447x; 2.1447x over previous
#include <cuda_runtime.h>
#include <cuda_bf16.h>
#include <math_constants.h>
#include <cstdint>
#include <cstddef>

#define T_DIM 2048
#define E_DIM 1024
#define M_DIM 32768
#define H_DIM 16
#define D_DIM 64
#define KCAND 8

// ---------------- device scratch (no allocations allowed) ----------------
__device__ float g_qkv[T_DIM * 3 * E_DIM];           // 24 MB  [T, 3E]
__device__ float g_y[T_DIM * E_DIM];                 // 8 MB   [T, E] attention out
__device__ float g_S[(size_t)T_DIM * M_DIM];         // 256 MB [T, M] coarse scores
__device__ float g_mknorm[M_DIM];                    // |mem_key|^2 (fp32)
__device__ int   g_cand[T_DIM * KCAND];              // top-8 candidates (coarse)
__device__ int   g_idx[T_DIM * 3];                   // exact top-3 indices
__device__ float g_comb[T_DIM * E_DIM];              // 8 MB combined
__device__ __nv_bfloat16 g_qbf[T_DIM * E_DIM];       // 4 MB  q in bf16
__device__ __nv_bfloat16 g_mkbf[(size_t)M_DIM * E_DIM]; // 64 MB mem keys bf16

// ---------------- SGEMM: C[M,N] = A[M,K] * B[N,K]^T (NT) ----------------
__global__ void __launch_bounds__(256)
sgemm_nt(const float* __restrict__ A, int lda,
         const float* __restrict__ B, int ldb,
         float* __restrict__ C, int ldc, int K) {
    __shared__ float As[8][132];
    __shared__ float Bs[8][132];
    const int tid = threadIdx.x;
    const int mBase = blockIdx.y * 128;
    const int nBase = blockIdx.x * 128;
    const int lr = tid >> 1;
    const int lc = (tid & 1) << 2;
    const float* Ag = A + (size_t)(mBase + lr) * lda + lc;
    const float* Bg = B + (size_t)(nBase + lr) * ldb + lc;
    const int tm = tid >> 4;
    const int tn = tid & 15;

    float acc[8][8];
#pragma unroll
    for (int i = 0; i < 8; i++)
#pragma unroll
        for (int j = 0; j < 8; j++) acc[i][j] = 0.0f;

    for (int k0 = 0; k0 < K; k0 += 8) {
        float4 av = *(const float4*)(Ag + k0);
        float4 bv = *(const float4*)(Bg + k0);
        __syncthreads();
        As[lc + 0][lr] = av.x; As[lc + 1][lr] = av.y;
        As[lc + 2][lr] = av.z; As[lc + 3][lr] = av.w;
        Bs[lc + 0][lr] = bv.x; Bs[lc + 1][lr] = bv.y;
        Bs[lc + 2][lr] = bv.z; Bs[lc + 3][lr] = bv.w;
        __syncthreads();
#pragma unroll
        for (int kk = 0; kk < 8; kk++) {
            float a[8], b[8];
            *(float4*)&a[0] = *(const float4*)&As[kk][tm * 8];
            *(float4*)&a[4] = *(const float4*)&As[kk][tm * 8 + 4];
            *(float4*)&b[0] = *(const float4*)&Bs[kk][tn * 8];
            *(float4*)&b[4] = *(const float4*)&Bs[kk][tn * 8 + 4];
#pragma unroll
            for (int i = 0; i < 8; i++)
#pragma unroll
                for (int j = 0; j < 8; j++)
                    acc[i][j] += a[i] * b[j];
        }
    }

#pragma unroll
    for (int i = 0; i < 8; i++) {
        size_t roff = (size_t)(mBase + tm * 8 + i) * ldc + nBase + tn * 8;
#pragma unroll
        for (int j = 0; j < 8; j += 4) {
            float4 v;
            v.x = acc[i][j]; v.y = acc[i][j + 1];
            v.z = acc[i][j + 2]; v.w = acc[i][j + 3];
            *(float4*)&C[roff + j] = v;
        }
    }
}

// ---------------- bf16 conversions ----------------
__global__ void __launch_bounds__(256)
cvt_q_kernel(const float* __restrict__ qkv, __nv_bfloat16* __restrict__ qb) {
    int i = blockIdx.x * 256 + threadIdx.x;
    int row = i >> 8;
    int c4 = (i & 255) * 4;
    float4 v = *(const float4*)&qkv[(size_t)row * 3072 + c4];
    __nv_bfloat162* o = (__nv_bfloat162*)&qb[(size_t)row * 1024 + c4];
    o[0] = __float22bfloat162_rn(make_float2(v.x, v.y));
    o[1] = __float22bfloat162_rn(make_float2(v.z, v.w));
}

__global__ void __launch_bounds__(256)
cvt_mk_kernel(const float* __restrict__ mem_db, __nv_bfloat16* __restrict__ kb) {
    int i = blockIdx.x * 256 + threadIdx.x;
    int row = i >> 8;
    int c4 = (i & 255) * 4;
    float4 v = *(const float4*)&mem_db[(size_t)row * 2048 + c4];
    __nv_bfloat162* o = (__nv_bfloat162*)&kb[(size_t)row * 1024 + c4];
    o[0] = __float22bfloat162_rn(make_float2(v.x, v.y));
    o[1] = __float22bfloat162_rn(make_float2(v.z, v.w));
}

// ---------------- mem-key squared norms ----------------
__global__ void mknorm_kernel(const float* __restrict__ mem_db) {
    int m = blockIdx.x * (blockDim.x >> 5) + (threadIdx.x >> 5);
    int lane = threadIdx.x & 31;
    if (m >= M_DIM) return;
    const float* row = mem_db + (size_t)m * 2 * E_DIM;
    float s = 0.0f;
    for (int e = lane; e < E_DIM; e += 32) {
        float v = row[e];
        s += v * v;
    }
#pragma unroll
    for (int o = 16; o; o >>= 1) s += __shfl_xor_sync(0xffffffffu, s, o);
    if (lane == 0) g_mknorm[m] = s;
}

// ---------------- bf16 tensor-core NT GEMM: S = -2 * A B^T + bias[n] ----
#define SROW 40   // smem row stride in bf16 elems (80 bytes)

__device__ __forceinline__ uint32_t smem_u32(const void* p) {
    return (uint32_t)__cvta_generic_to_shared(p);
}

__global__ void __launch_bounds__(256)
gemm_bf16_nt(const __nv_bfloat16* __restrict__ A,
             const __nv_bfloat16* __restrict__ B,
             float* __restrict__ C,
             const float* __restrict__ bias) {
    __shared__ __nv_bfloat16 As[2][128 * SROW];
    __shared__ __nv_bfloat16 Bs[2][128 * SROW];
    const int tid = threadIdx.x;
    const int mBase = blockIdx.y * 128;
    const int nBase = blockIdx.x * 128;
    const int lrow = tid >> 2;
    const int lchunk = tid & 3;
    const int warp = tid >> 5, lane = tid & 31;
    const int wm = warp & 1, wn = warp >> 1;

    float acc[4][4][4];
#pragma unroll
    for (int a = 0; a < 4; a++)
#pragma unroll
        for (int b = 0; b < 4; b++)
#pragma unroll
            for (int c = 0; c < 4; c++) acc[a][b][c] = 0.0f;

#define LOAD_STAGE(st, k0)                                                      \
    {                                                                           \
        _Pragma("unroll")                                                       \
        for (int half = 0; half < 2; half++) {                                  \
            int row = lrow + half * 64;                                         \
            uint32_t sa = smem_u32(&As[st][row * SROW + lchunk * 8]);           \
            const void* ga = A + (size_t)(mBase + row) * 1024 + (k0) + lchunk * 8; \
            asm volatile("cp.async.cg.shared.global [%0],[%1],16;\n"            \
                         :: "r"(sa), "l"(ga));                                  \
            uint32_t sb = smem_u32(&Bs[st][row * SROW + lchunk * 8]);           \
            const void* gb = B + (size_t)(nBase + row) * 1024 + (k0) + lchunk * 8; \
            asm volatile("cp.async.cg.shared.global [%0],[%1],16;\n"            \
                         :: "r"(sb), "l"(gb));                                  \
        }                                                                       \
        asm volatile("cp.async.commit_group;\n");                               \
    }

    LOAD_STAGE(0, 0)

    for (int ks = 0; ks < 32; ks++) {
        if (ks + 1 < 32) {
            LOAD_STAGE((ks + 1) & 1, (ks + 1) * 32)
            asm volatile("cp.async.wait_group 1;\n");
        } else {
            asm volatile("cp.async.wait_group 0;\n");
        }
        __syncthreads();
        const __nv_bfloat16* as = As[ks & 1];
        const __nv_bfloat16* bs = Bs[ks & 1];
#pragma unroll
        for (int kk = 0; kk < 32; kk += 16) {
            uint32_t af[4][4], bf[4][2];
#pragma unroll
            for (int mt = 0; mt < 4; mt++) {
                int base = wm * 64 + mt * 16;
                int r = lane & 7;
                int sel = lane >> 3;
                int row = base + ((sel & 1) ? 8 : 0) + r;
                int col = kk + ((sel & 2) ? 8 : 0);
                uint32_t addr = smem_u32(&as[row * SROW + col]);
                asm volatile(
                    "ldmatrix.sync.aligned.m8n8.x4.shared.b16 {%0,%1,%2,%3},[%4];\n"
                    : "=r"(af[mt][0]), "=r"(af[mt][1]),
                      "=r"(af[mt][2]), "=r"(af[mt][3])
                    : "r"(addr));
            }
#pragma unroll
            for (int nt = 0; nt < 4; nt++) {
                int base = wn * 32 + nt * 8;
                int r = lane & 7;
                int sel = (lane >> 3) & 1;
                int row = base + r;
                int col = kk + (sel ? 8 : 0);
                uint32_t addr = smem_u32(&bs[row * SROW + col]);
                asm volatile(
                    "ldmatrix.sync.aligned.m8n8.x2.shared.b16 {%0,%1},[%2];\n"
                    : "=r"(bf[nt][0]), "=r"(bf[nt][1])
                    : "r"(addr));
            }
#pragma unroll
            for (int mt = 0; mt < 4; mt++)
#pragma unroll
                for (int nt = 0; nt < 4; nt++)
                    asm volatile(
                        "mma.sync.aligned.m16n8k16.row.col.f32.bf16.bf16.f32 "
                        "{%0,%1,%2,%3},{%4,%5,%6,%7},{%8,%9},{%0,%1,%2,%3};\n"
                        : "+f"(acc[mt][nt][0]), "+f"(acc[mt][nt][1]),
                          "+f"(acc[mt][nt][2]), "+f"(acc[mt][nt][3])
                        : "r"(af[mt][0]), "r"(af[mt][1]),
                          "r"(af[mt][2]), "r"(af[mt][3]),
                          "r"(bf[nt][0]), "r"(bf[nt][1]));
        }
        __syncthreads();
    }

    const int r = lane >> 2, c = (lane & 3) * 2;
#pragma unroll
    for (int mt = 0; mt < 4; mt++) {
#pragma unroll
        for (int nt = 0; nt < 4; nt++) {
            int row0 = mBase + wm * 64 + mt * 16 + r;
            int col = nBase + wn * 32 + nt * 8 + c;
            float b0 = bias[col], b1 = bias[col + 1];
            size_t o0 = (size_t)row0 * M_DIM + col;
            float2 v0 = make_float2(-2.0f * acc[mt][nt][0] + b0,
                                    -2.0f * acc[mt][nt][1] + b1);
            *(float2*)&C[o0] = v0;
            size_t o1 = o0 + (size_t)8 * M_DIM;
            float2 v1 = make_float2(-2.0f * acc[mt][nt][2] + b0,
                                    -2.0f * acc[mt][nt][3] + b1);
            *(float2*)&C[o1] = v1;
        }
    }
#undef LOAD_STAGE
}

// ---------------- causal flash attention, fp32 ----------------
__global__ void __launch_bounds__(256)
flash_kernel(const float* __restrict__ qkv, float* __restrict__ y) {
    extern __shared__ float sm[];
    float* Qs = sm;
    float* Ks = Qs + 64 * 64;
    float* Vs = Ks + 64 * 68;
    float* Ss = Vs + 64 * 68;
    float* m_s = Ss + 64 * 64;
    float* l_s = m_s + 64;
    float* corr_s = l_s + 64;
    float* red = corr_s + 64;

    const int h = blockIdx.y;
    const int qt = blockIdx.x;
    const int tid = threadIdx.x;
    const int qbase = qt * 64;
    const int LDQ = 3 * E_DIM;

#pragma unroll
    for (int it = 0; it < 4; it++) {
        int idx = tid + it * 256;
        int r = idx >> 4, c4 = (idx & 15) << 2;
        *(float4*)&Qs[r * 64 + c4] =
            *(const float4*)&qkv[(size_t)(qbase + r) * LDQ + h * 64 + c4];
    }
    if (tid < 64) { m_s[tid] = -CUDART_INF_F; l_s[tid] = 0.0f; }

    const int tm = tid >> 4, tn = tid & 15;
    const int q0 = tm * 4, n0 = tn * 4;
    float acc[4][4] = {};

    for (int kt = 0; kt <= qt; kt++) {
        const int kbase = kt * 64;
        __syncthreads();
#pragma unroll
        for (int it = 0; it < 4; it++) {
            int idx = tid + it * 256;
            int r = idx >> 4, c4 = (idx & 15) << 2;
            size_t rowoff = (size_t)(kbase + r) * LDQ + h * 64 + c4;
            *(float4*)&Ks[r * 68 + c4] = *(const float4*)&qkv[rowoff + E_DIM];
            *(float4*)&Vs[r * 68 + c4] = *(const float4*)&qkv[rowoff + 2 * E_DIM];
        }
        __syncthreads();

        float s[4][4] = {};
#pragma unroll 8
        for (int d = 0; d < 64; d++) {
            float a[4], b[4];
#pragma unroll
            for (int i = 0; i < 4; i++) a[i] = Qs[(q0 + i) * 64 + d];
#pragma unroll
            for (int j = 0; j < 4; j++) b[j] = Ks[(n0 + j) * 68 + d];
#pragma unroll
            for (int i = 0; i < 4; i++)
#pragma unroll
                for (int j = 0; j < 4; j++) s[i][j] += a[i] * b[j];
        }
        const bool diag = (kt == qt);
#pragma unroll
        for (int i = 0; i < 4; i++)
#pragma unroll
            for (int j = 0; j < 4; j++) {
                float v = s[i][j] * 0.125f;
                if (diag && (n0 + j) > (q0 + i)) v = -CUDART_INF_F;
                Ss[(q0 + i) * 64 + (n0 + j)] = v;
            }
        __syncthreads();

        const int r = tid >> 2, p = tid & 3;
        float mx = -CUDART_INF_F;
#pragma unroll
        for (int c = 0; c < 16; c++) mx = fmaxf(mx, Ss[r * 64 + p * 16 + c]);
        red[r * 4 + p] = mx;
        __syncthreads();
        if (p == 0) {
            float mt = fmaxf(fmaxf(red[r * 4], red[r * 4 + 1]),
                             fmaxf(red[r * 4 + 2], red[r * 4 + 3]));
            float mold = m_s[r];
            float mnew = fmaxf(mold, mt);
            corr_s[r] = expf(mold - mnew);
            m_s[r] = mnew;
        }
        __syncthreads();
        float mnew = m_s[r];
        float ps = 0.0f;
#pragma unroll
        for (int c = 0; c < 16; c++) {
            float e = expf(Ss[r * 64 + p * 16 + c] - mnew);
            Ss[r * 64 + p * 16 + c] = e;
            ps += e;
        }
        red[r * 4 + p] = ps;
        __syncthreads();
        if (p == 0)
            l_s[r] = l_s[r] * corr_s[r] +
                     red[r * 4] + red[r * 4 + 1] + red[r * 4 + 2] + red[r * 4 + 3];

        float cr[4];
#pragma unroll
        for (int i = 0; i < 4; i++) cr[i] = corr_s[q0 + i];
#pragma unroll
        for (int i = 0; i < 4; i++)
#pragma unroll
            for (int j = 0; j < 4; j++) acc[i][j] *= cr[i];
#pragma unroll 8
        for (int kk = 0; kk < 64; kk++) {
            float pv[4], vv[4];
#pragma unroll
            for (int i = 0; i < 4; i++) pv[i] = Ss[(q0 + i) * 64 + kk];
#pragma unroll
            for (int j = 0; j < 4; j++) vv[j] = Vs[kk * 68 + n0 + j];
#pragma unroll
            for (int i = 0; i < 4; i++)
#pragma unroll
                for (int j = 0; j < 4; j++) acc[i][j] += pv[i] * vv[j];
        }
    }
    __syncthreads();
    float linv[4];
#pragma unroll
    for (int i = 0; i < 4; i++) linv[i] = 1.0f / l_s[q0 + i];
#pragma unroll
    for (int i = 0; i < 4; i++)
#pragma unroll
        for (int j = 0; j < 4; j++)
            y[(size_t)(qbase + q0 + i) * E_DIM + h * 64 + n0 + j] =
                acc[i][j] * linv[i];
}

// ---------------- candidate top-8 (coarse, bf16-derived scores) ----------
__device__ __forceinline__ bool lt_pair(float v, int i, float w, int j) {
    return (v < w) || (v == w && i < j);
}

__global__ void __launch_bounds__(256) top8_kernel(const float* __restrict__ S) {
    __shared__ float sv[256][KCAND];
    __shared__ int   si[256][KCAND];
    const int t = blockIdx.x;
    const int tid = threadIdx.x;
    const float* row = S + (size_t)t * M_DIM;
    float v[KCAND];
    int ix[KCAND];
#pragma unroll
    for (int k = 0; k < KCAND; k++) { v[k] = CUDART_INF_F; ix[k] = 0x7fffffff; }

    for (int j = tid; j < M_DIM; j += 256) {
        float val = row[j];
        if (lt_pair(val, j, v[KCAND - 1], ix[KCAND - 1])) {
            v[KCAND - 1] = val; ix[KCAND - 1] = j;
#pragma unroll
            for (int k = KCAND - 1; k > 0; k--) {
                if (lt_pair(v[k], ix[k], v[k - 1], ix[k - 1])) {
                    float tv = v[k]; v[k] = v[k - 1]; v[k - 1] = tv;
                    int ti = ix[k]; ix[k] = ix[k - 1]; ix[k - 1] = ti;
                } else break;
            }
        }
    }
#pragma unroll
    for (int k = 0; k < KCAND; k++) { sv[tid][k] = v[k]; si[tid][k] = ix[k]; }
    for (int s = 128; s > 0; s >>= 1) {
        __syncthreads();
        if (tid < s) {
#pragma unroll
            for (int k = 0; k < KCAND; k++) {
                float val = sv[tid + s][k];
                int idx = si[tid + s][k];
                if (lt_pair(val, idx, v[KCAND - 1], ix[KCAND - 1])) {
                    v[KCAND - 1] = val; ix[KCAND - 1] = idx;
#pragma unroll
                    for (int q = KCAND - 1; q > 0; q--) {
                        if (lt_pair(v[q], ix[q], v[q - 1], ix[q - 1])) {
                            float tv = v[q]; v[q] = v[q - 1]; v[q - 1] = tv;
                            int ti = ix[q]; ix[q] = ix[q - 1]; ix[q - 1] = ti;
                        } else break;
                    }
                }
            }
#pragma unroll
            for (int k = 0; k < KCAND; k++) { sv[tid][k] = v[k]; si[tid][k] = ix[k]; }
        }
    }
    if (tid == 0) {
#pragma unroll
        for (int k = 0; k < KCAND; k++) g_cand[t * KCAND + k] = ix[k];
    }
}

// ---------------- exact fp32 rescore of 8 candidates -> top-3 ------------
// block per token, warp w handles candidate w.
__global__ void __launch_bounds__(256)
rescore_kernel(const float* __restrict__ qkv,
               const float* __restrict__ mem_db,
               const float* __restrict__ mknorm) {
    __shared__ float sc[KCAND];
    __shared__ int   sidx[KCAND];
    const int t = blockIdx.x;
    const int w = threadIdx.x >> 5;
    const int lane = threadIdx.x & 31;
    const int cand = g_cand[t * KCAND + w];

    const float* qrow = qkv + (size_t)t * 3 * E_DIM;         // q part
    const float* krow = mem_db + (size_t)cand * 2 * E_DIM;   // key part
    float dot = 0.0f;
#pragma unroll
    for (int c = 0; c < 8; c++) {
        int e = (lane + c * 32) * 4;
        float4 qv = *(const float4*)&qrow[e];
        float4 kv = *(const float4*)&krow[e];
        dot += qv.x * kv.x + qv.y * kv.y + qv.z * kv.z + qv.w * kv.w;
    }
#pragma unroll
    for (int o = 16; o; o >>= 1) dot += __shfl_xor_sync(0xffffffffu, dot, o);
    if (lane == 0) {
        sc[w] = mknorm[cand] - 2.0f * dot;
        sidx[w] = cand;
    }
    __syncthreads();
    if (threadIdx.x == 0) {
        float v0 = CUDART_INF_F, v1 = CUDART_INF_F, v2 = CUDART_INF_F;
        int i0 = 0x7fffffff, i1 = 0x7fffffff, i2 = 0x7fffffff;
#pragma unroll
        for (int k = 0; k < KCAND; k++) {
            float val = sc[k]; int idx = sidx[k];
            if (lt_pair(val, idx, v2, i2)) {
                if (lt_pair(val, idx, v1, i1)) {
                    v2 = v1; i2 = i1;
                    if (lt_pair(val, idx, v0, i0)) {
                        v1 = v0; i1 = i0; v0 = val; i0 = idx;
                    } else { v1 = val; i1 = idx; }
                } else { v2 = val; i2 = idx; }
            }
        }
        g_idx[t * 3 + 0] = i0;
        g_idx[t * 3 + 1] = i1;
        g_idx[t * 3 + 2] = i2;
    }
}

// ---------------- gather + 3-way mem softmax + gated combine -------------
__global__ void __launch_bounds__(512)
memattn_kernel(const float* __restrict__ qkv,
               const float* __restrict__ mem_db,
               const float* __restrict__ y,
               const float* __restrict__ gate) {
    const int t = blockIdx.x;
    const int h = threadIdx.x >> 5;
    const int lane = threadIdx.x & 31;
    int id0 = g_idx[t * 3 + 0];
    int id1 = g_idx[t * 3 + 1];
    int id2 = g_idx[t * 3 + 2];
    const int d0 = lane * 2;
    size_t qoff = (size_t)t * 3 * E_DIM + h * 64 + d0;
    float q0 = qkv[qoff], q1 = qkv[qoff + 1];

    const float* k0p = mem_db + (size_t)id0 * 2 * E_DIM + h * 64;
    const float* k1p = mem_db + (size_t)id1 * 2 * E_DIM + h * 64;
    const float* k2p = mem_db + (size_t)id2 * 2 * E_DIM + h * 64;
    float s0 = q0 * k0p[d0] + q1 * k0p[d0 + 1];
    float s1 = q0 * k1p[d0] + q1 * k1p[d0 + 1];
    float s2 = q0 * k2p[d0] + q1 * k2p[d0 + 1];
#pragma unroll
    for (int o = 16; o; o >>= 1) {
        s0 += __shfl_xor_sync(0xffffffffu, s0, o);
        s1 += __shfl_xor_sync(0xffffffffu, s1, o);
        s2 += __shfl_xor_sync(0xffffffffu, s2, o);
    }
    s0 *= 4096.0f; s1 *= 4096.0f; s2 *= 4096.0f;
    float m = fmaxf(s0, fmaxf(s1, s2));
    float e0 = expf(s0 - m), e1 = expf(s1 - m), e2 = expf(s2 - m);
    float inv = 1.0f / (e0 + e1 + e2);
    e0 *= inv; e1 *= inv; e2 *= inv;

    const float* v0p = k0p + E_DIM;
    const float* v1p = k1p + E_DIM;
    const float* v2p = k2p + E_DIM;
    float o0 = e0 * v0p[d0] + e1 * v1p[d0] + e2 * v2p[d0];
    float o1 = e0 * v0p[d0 + 1] + e1 * v1p[d0 + 1] + e2 * v2p[d0 + 1];

    float g = gate[h];
    size_t off = (size_t)t * E_DIM + h * 64 + d0;
    g_comb[off]     = o0 * g + y[off] * (1.0f - g);
    g_comb[off + 1] = o1 * g + y[off + 1] * (1.0f - g);
}

// ---------------- launch ----------------
extern "C" void kernel_launch(void* const* d_in, const int* in_sizes, int n_in,
                              void* d_out, int out_size) {
    const float* x = nullptr;
    const float* mem_db = nullptr;
    const float* W_attn = nullptr;
    const float* W_proj = nullptr;
    const float* gate = nullptr;
    for (int i = 0; i < n_in; i++) {
        switch (in_sizes[i]) {
            case 2048 * 1024:       x      = (const float*)d_in[i]; break;
            case 32768 * 2048:      mem_db = (const float*)d_in[i]; break;
            case 3072 * 1024:       W_attn = (const float*)d_in[i]; break;
            case 1024 * 1024:       W_proj = (const float*)d_in[i]; break;
            case 16:                gate   = (const float*)d_in[i]; break;
            default: break;
        }
    }
    float* out = (float*)d_out;

    void *p_qkv, *p_y, *p_S, *p_comb, *p_mkn, *p_qbf, *p_mkbf;
    cudaGetSymbolAddress(&p_qkv, g_qkv);
    cudaGetSymbolAddress(&p_y, g_y);
    cudaGetSymbolAddress(&p_S, g_S);
    cudaGetSymbolAddress(&p_comb, g_comb);
    cudaGetSymbolAddress(&p_mkn, g_mknorm);
    cudaGetSymbolAddress(&p_qbf, g_qbf);
    cudaGetSymbolAddress(&p_mkbf, g_mkbf);
    float* qkv = (float*)p_qkv;
    float* y = (float*)p_y;
    float* S = (float*)p_S;
    float* comb = (float*)p_comb;
    float* mkn = (float*)p_mkn;
    __nv_bfloat16* qbf = (__nv_bfloat16*)p_qbf;
    __nv_bfloat16* mkbf = (__nv_bfloat16*)p_mkbf;

    const int FLASH_SMEM = (64 * 64 + 64 * 68 + 64 * 68 + 64 * 64 + 64 * 3 + 64 * 4) * 4;
    cudaFuncSetAttribute(flash_kernel,
                         cudaFuncAttributeMaxDynamicSharedMemorySize, FLASH_SMEM);

    // 1) qkv = x @ W_attn^T : [2048, 3072]
    sgemm_nt<<<dim3(3072 / 128, 2048 / 128), 256>>>(
        x, E_DIM, W_attn, E_DIM, qkv, 3 * E_DIM, E_DIM);

    // 2) |mem_key|^2 and bf16 conversions
    mknorm_kernel<<<M_DIM / 8, 256>>>(mem_db);
    cvt_mk_kernel<<<M_DIM, 256>>>(mem_db, mkbf);
    cvt_q_kernel<<<T_DIM, 256>>>(qkv, qbf);

    // 3) causal attention -> y [T, E]
    flash_kernel<<<dim3(T_DIM / 64, H_DIM), 256, FLASH_SMEM>>>(qkv, y);

    // 4) coarse S = -2 q @ mem_keys^T + |mk|^2  (bf16 tensor cores)
    gemm_bf16_nt<<<dim3(M_DIM / 128, T_DIM / 128), 256>>>(qbf, mkbf, S, mkn);

    // 5) coarse top-8 candidates, then exact fp32 rescore -> top-3
    top8_kernel<<<T_DIM, 256>>>(S);
    rescore_kernel<<<T_DIM, 256>>>(qkv, mem_db, mkn);

    // 6) mem attention + gated combine -> comb [T, E]
    memattn_kernel<<<T_DIM, 512>>>(qkv, mem_db, y, gate);

    // 7) out = comb @ W_proj^T
    sgemm_nt<<<dim3(1024 / 128, 2048 / 128), 256>>>(
        comb, E_DIM, W_proj, E_DIM, out, E_DIM, E_DIM);
}

// round 4
// speedup vs baseline: 3.2232x; 1.5029x over previous
#include <cuda_runtime.h>
#include <cuda_bf16.h>
#include <math_constants.h>
#include <cstdint>
#include <cstddef>

#define T_DIM 2048
#define E_DIM 1024
#define M_DIM 32768
#define H_DIM 16
#define D_DIM 64
#define KCAND 8

// ---------------- device scratch ----------------
__device__ float g_qkv[T_DIM * 3 * E_DIM];
__device__ float g_y[T_DIM * E_DIM];
__device__ float g_S[(size_t)T_DIM * M_DIM];
__device__ float g_mknorm[M_DIM];
__device__ int   g_cand[T_DIM * KCAND];
__device__ int   g_idx[T_DIM * 3];
__device__ float g_comb[T_DIM * E_DIM];
__device__ __nv_bfloat16 g_qbf[T_DIM * E_DIM];
__device__ __nv_bfloat16 g_mkbf[(size_t)M_DIM * E_DIM];

__device__ __forceinline__ uint32_t smem_u32(const void* p) {
    return (uint32_t)__cvta_generic_to_shared(p);
}
__device__ __forceinline__ uint32_t f2tf32(float f) {
    uint32_t u;
    asm("cvt.rna.tf32.f32 %0,%1;" : "=r"(u) : "f"(f));
    return u;
}
__device__ __forceinline__ float f2tf32f(float f) {
    return __uint_as_float(f2tf32(f));
}

// ---------------- fp32 SGEMM (NT) — kept for the ranking-exact q path ----
__global__ void __launch_bounds__(256)
sgemm_nt(const float* __restrict__ A, int lda,
         const float* __restrict__ B, int ldb,
         float* __restrict__ C, int ldc, int K) {
    __shared__ float As[8][132];
    __shared__ float Bs[8][132];
    const int tid = threadIdx.x;
    const int mBase = blockIdx.y * 128;
    const int nBase = blockIdx.x * 128;
    const int lr = tid >> 1;
    const int lc = (tid & 1) << 2;
    const float* Ag = A + (size_t)(mBase + lr) * lda + lc;
    const float* Bg = B + (size_t)(nBase + lr) * ldb + lc;
    const int tm = tid >> 4;
    const int tn = tid & 15;

    float acc[8][8];
#pragma unroll
    for (int i = 0; i < 8; i++)
#pragma unroll
        for (int j = 0; j < 8; j++) acc[i][j] = 0.0f;

    for (int k0 = 0; k0 < K; k0 += 8) {
        float4 av = *(const float4*)(Ag + k0);
        float4 bv = *(const float4*)(Bg + k0);
        __syncthreads();
        As[lc + 0][lr] = av.x; As[lc + 1][lr] = av.y;
        As[lc + 2][lr] = av.z; As[lc + 3][lr] = av.w;
        Bs[lc + 0][lr] = bv.x; Bs[lc + 1][lr] = bv.y;
        Bs[lc + 2][lr] = bv.z; Bs[lc + 3][lr] = bv.w;
        __syncthreads();
#pragma unroll
        for (int kk = 0; kk < 8; kk++) {
            float a[8], b[8];
            *(float4*)&a[0] = *(const float4*)&As[kk][tm * 8];
            *(float4*)&a[4] = *(const float4*)&As[kk][tm * 8 + 4];
            *(float4*)&b[0] = *(const float4*)&Bs[kk][tn * 8];
            *(float4*)&b[4] = *(const float4*)&Bs[kk][tn * 8 + 4];
#pragma unroll
            for (int i = 0; i < 8; i++)
#pragma unroll
                for (int j = 0; j < 8; j++)
                    acc[i][j] += a[i] * b[j];
        }
    }

#pragma unroll
    for (int i = 0; i < 8; i++) {
        size_t roff = (size_t)(mBase + tm * 8 + i) * ldc + nBase + tn * 8;
#pragma unroll
        for (int j = 0; j < 8; j += 4) {
            float4 v;
            v.x = acc[i][j]; v.y = acc[i][j + 1];
            v.z = acc[i][j + 2]; v.w = acc[i][j + 3];
            *(float4*)&C[roff + j] = v;
        }
    }
}

// ---------------- tf32 tensor-core NT GEMM: C = A B^T ----------------
// A [M,K], B [N,K] row-major fp32; C fp32. Tiles 128x128, k-step 16.
// smem layout [row][k] stride 20 -> conflict-free fragment loads.
__global__ void __launch_bounds__(256)
gemm_tf32_nt(const float* __restrict__ A, int lda,
             const float* __restrict__ B, int ldb,
             float* __restrict__ C, int ldc, int K) {
    __shared__ float As[2][128 * 20];
    __shared__ float Bs[2][128 * 20];
    const int tid = threadIdx.x;
    const int mBase = blockIdx.y * 128;
    const int nBase = blockIdx.x * 128;
    const int lrow = tid >> 2;          // 0..63
    const int k4 = (tid & 3) * 4;       // 16B chunk within k16
    const int warp = tid >> 5, lane = tid & 31;
    const int wm = warp & 3, wn = warp >> 2;   // 4 x 2 warps, 32x64 tiles

    float acc[2][8][4];
#pragma unroll
    for (int a = 0; a < 2; a++)
#pragma unroll
        for (int b = 0; b < 8; b++)
#pragma unroll
            for (int c = 0; c < 4; c++) acc[a][b][c] = 0.0f;

#define GL_STAGE(st, k0)                                                        \
    {                                                                           \
        _Pragma("unroll")                                                       \
        for (int half = 0; half < 2; half++) {                                  \
            int row = lrow + half * 64;                                         \
            uint32_t sa = smem_u32(&As[st][row * 20 + k4]);                     \
            const void* ga = A + (size_t)(mBase + row) * lda + (k0) + k4;       \
            asm volatile("cp.async.cg.shared.global [%0],[%1],16;\n"            \
                         :: "r"(sa), "l"(ga));                                  \
            uint32_t sb = smem_u32(&Bs[st][row * 20 + k4]);                     \
            const void* gb = B + (size_t)(nBase + row) * ldb + (k0) + k4;       \
            asm volatile("cp.async.cg.shared.global [%0],[%1],16;\n"            \
                         :: "r"(sb), "l"(gb));                                  \
        }                                                                       \
        asm volatile("cp.async.commit_group;\n");                               \
    }

    GL_STAGE(0, 0)
    const int KS = K / 16;
    for (int ks = 0; ks < KS; ks++) {
        if (ks + 1 < KS) {
            GL_STAGE((ks + 1) & 1, (ks + 1) * 16)
            asm volatile("cp.async.wait_group 1;\n");
        } else {
            asm volatile("cp.async.wait_group 0;\n");
        }
        __syncthreads();
        const float* as = As[ks & 1];
        const float* bs = Bs[ks & 1];
#pragma unroll
        for (int kk = 0; kk < 16; kk += 8) {
            uint32_t af[2][4], bf[8][2];
#pragma unroll
            for (int mt = 0; mt < 2; mt++) {
                int r0 = wm * 32 + mt * 16 + (lane >> 2);
                int c0 = kk + (lane & 3);
                af[mt][0] = f2tf32(as[r0 * 20 + c0]);
                af[mt][1] = f2tf32(as[(r0 + 8) * 20 + c0]);
                af[mt][2] = f2tf32(as[r0 * 20 + c0 + 4]);
                af[mt][3] = f2tf32(as[(r0 + 8) * 20 + c0 + 4]);
            }
#pragma unroll
            for (int nt = 0; nt < 8; nt++) {
                int n0 = wn * 64 + nt * 8 + (lane >> 2);
                int c0 = kk + (lane & 3);
                bf[nt][0] = f2tf32(bs[n0 * 20 + c0]);
                bf[nt][1] = f2tf32(bs[n0 * 20 + c0 + 4]);
            }
#pragma unroll
            for (int mt = 0; mt < 2; mt++)
#pragma unroll
                for (int nt = 0; nt < 8; nt++)
                    asm volatile(
                        "mma.sync.aligned.m16n8k8.row.col.f32.tf32.tf32.f32 "
                        "{%0,%1,%2,%3},{%4,%5,%6,%7},{%8,%9},{%0,%1,%2,%3};\n"
                        : "+f"(acc[mt][nt][0]), "+f"(acc[mt][nt][1]),
                          "+f"(acc[mt][nt][2]), "+f"(acc[mt][nt][3])
                        : "r"(af[mt][0]), "r"(af[mt][1]),
                          "r"(af[mt][2]), "r"(af[mt][3]),
                          "r"(bf[nt][0]), "r"(bf[nt][1]));
        }
        __syncthreads();
    }

    const int r = lane >> 2, c = (lane & 3) * 2;
#pragma unroll
    for (int mt = 0; mt < 2; mt++) {
#pragma unroll
        for (int nt = 0; nt < 8; nt++) {
            int row0 = mBase + wm * 32 + mt * 16 + r;
            int col = nBase + wn * 64 + nt * 8 + c;
            *(float2*)&C[(size_t)row0 * ldc + col] =
                make_float2(acc[mt][nt][0], acc[mt][nt][1]);
            *(float2*)&C[(size_t)(row0 + 8) * ldc + col] =
                make_float2(acc[mt][nt][2], acc[mt][nt][3]);
        }
    }
#undef GL_STAGE
}

// ---------------- bf16 conversions ----------------
__global__ void __launch_bounds__(256)
cvt_q_kernel(const float* __restrict__ qkv, __nv_bfloat16* __restrict__ qb) {
    int i = blockIdx.x * 256 + threadIdx.x;
    int row = i >> 8;
    int c4 = (i & 255) * 4;
    float4 v = *(const float4*)&qkv[(size_t)row * 3072 + c4];
    __nv_bfloat162* o = (__nv_bfloat162*)&qb[(size_t)row * 1024 + c4];
    o[0] = __float22bfloat162_rn(make_float2(v.x, v.y));
    o[1] = __float22bfloat162_rn(make_float2(v.z, v.w));
}

__global__ void __launch_bounds__(256)
cvt_mk_kernel(const float* __restrict__ mem_db, __nv_bfloat16* __restrict__ kb) {
    int i = blockIdx.x * 256 + threadIdx.x;
    int row = i >> 8;
    int c4 = (i & 255) * 4;
    float4 v = *(const float4*)&mem_db[(size_t)row * 2048 + c4];
    __nv_bfloat162* o = (__nv_bfloat162*)&kb[(size_t)row * 1024 + c4];
    o[0] = __float22bfloat162_rn(make_float2(v.x, v.y));
    o[1] = __float22bfloat162_rn(make_float2(v.z, v.w));
}

// ---------------- mem-key squared norms ----------------
__global__ void mknorm_kernel(const float* __restrict__ mem_db) {
    int m = blockIdx.x * (blockDim.x >> 5) + (threadIdx.x >> 5);
    int lane = threadIdx.x & 31;
    if (m >= M_DIM) return;
    const float* row = mem_db + (size_t)m * 2 * E_DIM;
    float s = 0.0f;
    for (int e = lane; e < E_DIM; e += 32) {
        float v = row[e];
        s += v * v;
    }
#pragma unroll
    for (int o = 16; o; o >>= 1) s += __shfl_xor_sync(0xffffffffu, s, o);
    if (lane == 0) g_mknorm[m] = s;
}

// ---------------- bf16 tensor-core NT GEMM (d2 coarse scores) ----------
#define SROW 40

__global__ void __launch_bounds__(256)
gemm_bf16_nt(const __nv_bfloat16* __restrict__ A,
             const __nv_bfloat16* __restrict__ B,
             float* __restrict__ C,
             const float* __restrict__ bias) {
    __shared__ __nv_bfloat16 As[2][128 * SROW];
    __shared__ __nv_bfloat16 Bs[2][128 * SROW];
    const int tid = threadIdx.x;
    const int mBase = blockIdx.y * 128;
    const int nBase = blockIdx.x * 128;
    const int lrow = tid >> 2;
    const int lchunk = tid & 3;
    const int warp = tid >> 5, lane = tid & 31;
    const int wm = warp & 1, wn = warp >> 1;

    float acc[4][4][4];
#pragma unroll
    for (int a = 0; a < 4; a++)
#pragma unroll
        for (int b = 0; b < 4; b++)
#pragma unroll
            for (int c = 0; c < 4; c++) acc[a][b][c] = 0.0f;

#define LOAD_STAGE(st, k0)                                                      \
    {                                                                           \
        _Pragma("unroll")                                                       \
        for (int half = 0; half < 2; half++) {                                  \
            int row = lrow + half * 64;                                         \
            uint32_t sa = smem_u32(&As[st][row * SROW + lchunk * 8]);           \
            const void* ga = A + (size_t)(mBase + row) * 1024 + (k0) + lchunk * 8; \
            asm volatile("cp.async.cg.shared.global [%0],[%1],16;\n"            \
                         :: "r"(sa), "l"(ga));                                  \
            uint32_t sb = smem_u32(&Bs[st][row * SROW + lchunk * 8]);           \
            const void* gb = B + (size_t)(nBase + row) * 1024 + (k0) + lchunk * 8; \
            asm volatile("cp.async.cg.shared.global [%0],[%1],16;\n"            \
                         :: "r"(sb), "l"(gb));                                  \
        }                                                                       \
        asm volatile("cp.async.commit_group;\n");                               \
    }

    LOAD_STAGE(0, 0)

    for (int ks = 0; ks < 32; ks++) {
        if (ks + 1 < 32) {
            LOAD_STAGE((ks + 1) & 1, (ks + 1) * 32)
            asm volatile("cp.async.wait_group 1;\n");
        } else {
            asm volatile("cp.async.wait_group 0;\n");
        }
        __syncthreads();
        const __nv_bfloat16* as = As[ks & 1];
        const __nv_bfloat16* bs = Bs[ks & 1];
#pragma unroll
        for (int kk = 0; kk < 32; kk += 16) {
            uint32_t af[4][4], bf[4][2];
#pragma unroll
            for (int mt = 0; mt < 4; mt++) {
                int base = wm * 64 + mt * 16;
                int r = lane & 7;
                int sel = lane >> 3;
                int row = base + ((sel & 1) ? 8 : 0) + r;
                int col = kk + ((sel & 2) ? 8 : 0);
                uint32_t addr = smem_u32(&as[row * SROW + col]);
                asm volatile(
                    "ldmatrix.sync.aligned.m8n8.x4.shared.b16 {%0,%1,%2,%3},[%4];\n"
                    : "=r"(af[mt][0]), "=r"(af[mt][1]),
                      "=r"(af[mt][2]), "=r"(af[mt][3])
                    : "r"(addr));
            }
#pragma unroll
            for (int nt = 0; nt < 4; nt++) {
                int base = wn * 32 + nt * 8;
                int r = lane & 7;
                int sel = (lane >> 3) & 1;
                int row = base + r;
                int col = kk + (sel ? 8 : 0);
                uint32_t addr = smem_u32(&bs[row * SROW + col]);
                asm volatile(
                    "ldmatrix.sync.aligned.m8n8.x2.shared.b16 {%0,%1},[%2];\n"
                    : "=r"(bf[nt][0]), "=r"(bf[nt][1])
                    : "r"(addr));
            }
#pragma unroll
            for (int mt = 0; mt < 4; mt++)
#pragma unroll
                for (int nt = 0; nt < 4; nt++)
                    asm volatile(
                        "mma.sync.aligned.m16n8k16.row.col.f32.bf16.bf16.f32 "
                        "{%0,%1,%2,%3},{%4,%5,%6,%7},{%8,%9},{%0,%1,%2,%3};\n"
                        : "+f"(acc[mt][nt][0]), "+f"(acc[mt][nt][1]),
                          "+f"(acc[mt][nt][2]), "+f"(acc[mt][nt][3])
                        : "r"(af[mt][0]), "r"(af[mt][1]),
                          "r"(af[mt][2]), "r"(af[mt][3]),
                          "r"(bf[nt][0]), "r"(bf[nt][1]));
        }
        __syncthreads();
    }

    const int r = lane >> 2, c = (lane & 3) * 2;
#pragma unroll
    for (int mt = 0; mt < 4; mt++) {
#pragma unroll
        for (int nt = 0; nt < 4; nt++) {
            int row0 = mBase + wm * 64 + mt * 16 + r;
            int col = nBase + wn * 32 + nt * 8 + c;
            float b0 = bias[col], b1 = bias[col + 1];
            size_t o0 = (size_t)row0 * M_DIM + col;
            float2 v0 = make_float2(-2.0f * acc[mt][nt][0] + b0,
                                    -2.0f * acc[mt][nt][1] + b1);
            *(float2*)&C[o0] = v0;
            size_t o1 = o0 + (size_t)8 * M_DIM;
            float2 v1 = make_float2(-2.0f * acc[mt][nt][2] + b0,
                                    -2.0f * acc[mt][nt][3] + b1);
            *(float2*)&C[o1] = v1;
        }
    }
#undef LOAD_STAGE
}

// ---------------- causal flash attention, tf32 tensor cores ----------------
// block = (q-tile of 64, head). 256 threads = 8 warps (4 M x 2 N), m16n8k8.
__global__ void __launch_bounds__(256)
flash_tf32_kernel(const float* __restrict__ qkv, float* __restrict__ y) {
    extern __shared__ float sm[];
    float* Qs = sm;                       // [64][68]
    float* Ks = Qs + 64 * 68;             // [64][68]
    float* Vs = Ks + 64 * 68;             // [64][68]
    float* Ss = Vs + 64 * 68;             // [64][68]
    float* m_s = Ss + 64 * 68;            // [64]
    float* l_s = m_s + 64;                // [64]
    float* corr_s = l_s + 64;             // [64]
    float* red = corr_s + 64;             // [256]

    const int h = blockIdx.y;
    const int qt = blockIdx.x;
    const int tid = threadIdx.x;
    const int qbase = qt * 64;
    const int LDQ = 3 * E_DIM;
    const int warp = tid >> 5, lane = tid & 31;
    const int wm = warp >> 1, wn = warp & 1;   // 4 x 2
    const int fr = lane >> 2, fc = lane & 3;   // fragment row/col ids

#pragma unroll
    for (int it = 0; it < 4; it++) {
        int idx = tid + it * 256;
        int r = idx >> 4, c4 = (idx & 15) << 2;
        float4 v = *(const float4*)&qkv[(size_t)(qbase + r) * LDQ + h * 64 + c4];
        Qs[r * 68 + c4 + 0] = f2tf32f(v.x);
        Qs[r * 68 + c4 + 1] = f2tf32f(v.y);
        Qs[r * 68 + c4 + 2] = f2tf32f(v.z);
        Qs[r * 68 + c4 + 3] = f2tf32f(v.w);
    }
    if (tid < 64) { m_s[tid] = -CUDART_INF_F; l_s[tid] = 0.0f; }

    float acc_o[4][4];
#pragma unroll
    for (int nt = 0; nt < 4; nt++)
#pragma unroll
        for (int c = 0; c < 4; c++) acc_o[nt][c] = 0.0f;

    for (int kt = 0; kt <= qt; kt++) {
        const int kbase = kt * 64;
        __syncthreads();  // protect Ks/Vs/Ss from previous iteration readers
#pragma unroll
        for (int it = 0; it < 4; it++) {
            int idx = tid + it * 256;
            int r = idx >> 4, c4 = (idx & 15) << 2;
            size_t rowoff = (size_t)(kbase + r) * LDQ + h * 64 + c4;
            float4 kv = *(const float4*)&qkv[rowoff + E_DIM];
            float4 vv = *(const float4*)&qkv[rowoff + 2 * E_DIM];
            Ks[r * 68 + c4 + 0] = f2tf32f(kv.x);
            Ks[r * 68 + c4 + 1] = f2tf32f(kv.y);
            Ks[r * 68 + c4 + 2] = f2tf32f(kv.z);
            Ks[r * 68 + c4 + 3] = f2tf32f(kv.w);
            Vs[r * 68 + c4 + 0] = f2tf32f(vv.x);
            Vs[r * 68 + c4 + 1] = f2tf32f(vv.y);
            Vs[r * 68 + c4 + 2] = f2tf32f(vv.z);
            Vs[r * 68 + c4 + 3] = f2tf32f(vv.w);
        }
        __syncthreads();

        // ---- phase A: S = Q K^T (tf32 mma) ----
        float sacc[4][4];
#pragma unroll
        for (int nt = 0; nt < 4; nt++)
#pragma unroll
            for (int c = 0; c < 4; c++) sacc[nt][c] = 0.0f;

#pragma unroll
        for (int kk = 0; kk < 64; kk += 8) {
            int r0 = wm * 16 + fr;
            uint32_t a0 = __float_as_uint(Qs[r0 * 68 + kk + fc]);
            uint32_t a1 = __float_as_uint(Qs[(r0 + 8) * 68 + kk + fc]);
            uint32_t a2 = __float_as_uint(Qs[r0 * 68 + kk + fc + 4]);
            uint32_t a3 = __float_as_uint(Qs[(r0 + 8) * 68 + kk + fc + 4]);
#pragma unroll
            for (int nt = 0; nt < 4; nt++) {
                int n0 = wn * 32 + nt * 8 + fr;
                uint32_t b0 = __float_as_uint(Ks[n0 * 68 + kk + fc]);
                uint32_t b1 = __float_as_uint(Ks[n0 * 68 + kk + fc + 4]);
                asm volatile(
                    "mma.sync.aligned.m16n8k8.row.col.f32.tf32.tf32.f32 "
                    "{%0,%1,%2,%3},{%4,%5,%6,%7},{%8,%9},{%0,%1,%2,%3};\n"
                    : "+f"(sacc[nt][0]), "+f"(sacc[nt][1]),
                      "+f"(sacc[nt][2]), "+f"(sacc[nt][3])
                    : "r"(a0), "r"(a1), "r"(a2), "r"(a3),
                      "r"(b0), "r"(b1));
            }
        }
        // scale + causal mask + store to Ss
        const bool diag = (kt == qt);
        {
            int r0 = wm * 16 + fr;
#pragma unroll
            for (int nt = 0; nt < 4; nt++) {
                int c0 = wn * 32 + nt * 8 + 2 * fc;
#pragma unroll
                for (int half = 0; half < 2; half++) {
                    int rr = r0 + half * 8;
                    float v0 = sacc[nt][half * 2 + 0] * 0.125f;
                    float v1 = sacc[nt][half * 2 + 1] * 0.125f;
                    if (diag && (c0 + 0) > rr) v0 = -CUDART_INF_F;
                    if (diag && (c0 + 1) > rr) v1 = -CUDART_INF_F;
                    *(float2*)&Ss[rr * 68 + c0] = make_float2(v0, v1);
                }
            }
        }
        __syncthreads();

        // ---- phase B: online softmax (4 threads per row) ----
        const int r = tid >> 2, p = tid & 3;
        float mx = -CUDART_INF_F;
#pragma unroll
        for (int c = 0; c < 16; c++) mx = fmaxf(mx, Ss[r * 68 + p * 16 + c]);
        red[r * 4 + p] = mx;
        __syncthreads();
        if (p == 0) {
            float mt = fmaxf(fmaxf(red[r * 4], red[r * 4 + 1]),
                             fmaxf(red[r * 4 + 2], red[r * 4 + 3]));
            float mold = m_s[r];
            float mnew = fmaxf(mold, mt);
            corr_s[r] = __expf(mold - mnew);
            m_s[r] = mnew;
        }
        __syncthreads();
        float mnew = m_s[r];
        float ps = 0.0f;
#pragma unroll
        for (int c = 0; c < 16; c++) {
            float e = f2tf32f(__expf(Ss[r * 68 + p * 16 + c] - mnew));
            Ss[r * 68 + p * 16 + c] = e;
            ps += e;
        }
        red[r * 4 + p] = ps;
        __syncthreads();
        if (p == 0)
            l_s[r] = l_s[r] * corr_s[r] +
                     red[r * 4] + red[r * 4 + 1] + red[r * 4 + 2] + red[r * 4 + 3];

        // ---- phase C: acc_o = acc_o * corr + P V (tf32 mma) ----
        {
            int r0 = wm * 16 + fr;
            float cr0 = corr_s[r0];
            float cr1 = corr_s[r0 + 8];
#pragma unroll
            for (int nt = 0; nt < 4; nt++) {
                acc_o[nt][0] *= cr0; acc_o[nt][1] *= cr0;
                acc_o[nt][2] *= cr1; acc_o[nt][3] *= cr1;
            }
#pragma unroll
            for (int kk = 0; kk < 64; kk += 8) {
                uint32_t a0 = __float_as_uint(Ss[r0 * 68 + kk + fc]);
                uint32_t a1 = __float_as_uint(Ss[(r0 + 8) * 68 + kk + fc]);
                uint32_t a2 = __float_as_uint(Ss[r0 * 68 + kk + fc + 4]);
                uint32_t a3 = __float_as_uint(Ss[(r0 + 8) * 68 + kk + fc + 4]);
#pragma unroll
                for (int nt = 0; nt < 4; nt++) {
                    int n0 = wn * 32 + nt * 8 + fr;
                    uint32_t b0 = __float_as_uint(Vs[(kk + fc) * 68 + n0]);
                    uint32_t b1 = __float_as_uint(Vs[(kk + fc + 4) * 68 + n0]);
                    asm volatile(
                        "mma.sync.aligned.m16n8k8.row.col.f32.tf32.tf32.f32 "
                        "{%0,%1,%2,%3},{%4,%5,%6,%7},{%8,%9},{%0,%1,%2,%3};\n"
                        : "+f"(acc_o[nt][0]), "+f"(acc_o[nt][1]),
                          "+f"(acc_o[nt][2]), "+f"(acc_o[nt][3])
                        : "r"(a0), "r"(a1), "r"(a2), "r"(a3),
                          "r"(b0), "r"(b1));
                }
            }
        }
    }
    __syncthreads();
    {
        int r0 = wm * 16 + fr;
        float linv0 = 1.0f / l_s[r0];
        float linv1 = 1.0f / l_s[r0 + 8];
#pragma unroll
        for (int nt = 0; nt < 4; nt++) {
            int c0 = h * 64 + wn * 32 + nt * 8 + 2 * fc;
            *(float2*)&y[(size_t)(qbase + r0) * E_DIM + c0] =
                make_float2(acc_o[nt][0] * linv0, acc_o[nt][1] * linv0);
            *(float2*)&y[(size_t)(qbase + r0 + 8) * E_DIM + c0] =
                make_float2(acc_o[nt][2] * linv1, acc_o[nt][3] * linv1);
        }
    }
}

// ---------------- candidate top-8 (coarse) ----------
__device__ __forceinline__ bool lt_pair(float v, int i, float w, int j) {
    return (v < w) || (v == w && i < j);
}

__global__ void __launch_bounds__(256) top8_kernel(const float* __restrict__ S) {
    __shared__ float sv[256][KCAND];
    __shared__ int   si[256][KCAND];
    const int t = blockIdx.x;
    const int tid = threadIdx.x;
    const float* row = S + (size_t)t * M_DIM;
    float v[KCAND];
    int ix[KCAND];
#pragma unroll
    for (int k = 0; k < KCAND; k++) { v[k] = CUDART_INF_F; ix[k] = 0x7fffffff; }

    for (int j = tid; j < M_DIM; j += 256) {
        float val = row[j];
        if (lt_pair(val, j, v[KCAND - 1], ix[KCAND - 1])) {
            v[KCAND - 1] = val; ix[KCAND - 1] = j;
#pragma unroll
            for (int k = KCAND - 1; k > 0; k--) {
                if (lt_pair(v[k], ix[k], v[k - 1], ix[k - 1])) {
                    float tv = v[k]; v[k] = v[k - 1]; v[k - 1] = tv;
                    int ti = ix[k]; ix[k] = ix[k - 1]; ix[k - 1] = ti;
                } else break;
            }
        }
    }
#pragma unroll
    for (int k = 0; k < KCAND; k++) { sv[tid][k] = v[k]; si[tid][k] = ix[k]; }
    for (int s = 128; s > 0; s >>= 1) {
        __syncthreads();
        if (tid < s) {
#pragma unroll
            for (int k = 0; k < KCAND; k++) {
                float val = sv[tid + s][k];
                int idx = si[tid + s][k];
                if (lt_pair(val, idx, v[KCAND - 1], ix[KCAND - 1])) {
                    v[KCAND - 1] = val; ix[KCAND - 1] = idx;
#pragma unroll
                    for (int q = KCAND - 1; q > 0; q--) {
                        if (lt_pair(v[q], ix[q], v[q - 1], ix[q - 1])) {
                            float tv = v[q]; v[q] = v[q - 1]; v[q - 1] = tv;
                            int ti = ix[q]; ix[q] = ix[q - 1]; ix[q - 1] = ti;
                        } else break;
                    }
                }
            }
#pragma unroll
            for (int k = 0; k < KCAND; k++) { sv[tid][k] = v[k]; si[tid][k] = ix[k]; }
        }
    }
    if (tid == 0) {
#pragma unroll
        for (int k = 0; k < KCAND; k++) g_cand[t * KCAND + k] = ix[k];
    }
}

// ---------------- exact fp32 rescore of 8 candidates -> top-3 ------------
__global__ void __launch_bounds__(256)
rescore_kernel(const float* __restrict__ qkv,
               const float* __restrict__ mem_db,
               const float* __restrict__ mknorm) {
    __shared__ float sc[KCAND];
    __shared__ int   sidx[KCAND];
    const int t = blockIdx.x;
    const int w = threadIdx.x >> 5;
    const int lane = threadIdx.x & 31;
    const int cand = g_cand[t * KCAND + w];

    const float* qrow = qkv + (size_t)t * 3 * E_DIM;
    const float* krow = mem_db + (size_t)cand * 2 * E_DIM;
    float dot = 0.0f;
#pragma unroll
    for (int c = 0; c < 8; c++) {
        int e = (lane + c * 32) * 4;
        float4 qv = *(const float4*)&qrow[e];
        float4 kv = *(const float4*)&krow[e];
        dot += qv.x * kv.x + qv.y * kv.y + qv.z * kv.z + qv.w * kv.w;
    }
#pragma unroll
    for (int o = 16; o; o >>= 1) dot += __shfl_xor_sync(0xffffffffu, dot, o);
    if (lane == 0) {
        sc[w] = mknorm[cand] - 2.0f * dot;
        sidx[w] = cand;
    }
    __syncthreads();
    if (threadIdx.x == 0) {
        float v0 = CUDART_INF_F, v1 = CUDART_INF_F, v2 = CUDART_INF_F;
        int i0 = 0x7fffffff, i1 = 0x7fffffff, i2 = 0x7fffffff;
#pragma unroll
        for (int k = 0; k < KCAND; k++) {
            float val = sc[k]; int idx = sidx[k];
            if (lt_pair(val, idx, v2, i2)) {
                if (lt_pair(val, idx, v1, i1)) {
                    v2 = v1; i2 = i1;
                    if (lt_pair(val, idx, v0, i0)) {
                        v1 = v0; i1 = i0; v0 = val; i0 = idx;
                    } else { v1 = val; i1 = idx; }
                } else { v2 = val; i2 = idx; }
            }
        }
        g_idx[t * 3 + 0] = i0;
        g_idx[t * 3 + 1] = i1;
        g_idx[t * 3 + 2] = i2;
    }
}

// ---------------- gather + 3-way mem softmax + gated combine -------------
__global__ void __launch_bounds__(512)
memattn_kernel(const float* __restrict__ qkv,
               const float* __restrict__ mem_db,
               const float* __restrict__ y,
               const float* __restrict__ gate) {
    const int t = blockIdx.x;
    const int h = threadIdx.x >> 5;
    const int lane = threadIdx.x & 31;
    int id0 = g_idx[t * 3 + 0];
    int id1 = g_idx[t * 3 + 1];
    int id2 = g_idx[t * 3 + 2];
    const int d0 = lane * 2;
    size_t qoff = (size_t)t * 3 * E_DIM + h * 64 + d0;
    float q0 = qkv[qoff], q1 = qkv[qoff + 1];

    const float* k0p = mem_db + (size_t)id0 * 2 * E_DIM + h * 64;
    const float* k1p = mem_db + (size_t)id1 * 2 * E_DIM + h * 64;
    const float* k2p = mem_db + (size_t)id2 * 2 * E_DIM + h * 64;
    float s0 = q0 * k0p[d0] + q1 * k0p[d0 + 1];
    float s1 = q0 * k1p[d0] + q1 * k1p[d0 + 1];
    float s2 = q0 * k2p[d0] + q1 * k2p[d0 + 1];
#pragma unroll
    for (int o = 16; o; o >>= 1) {
        s0 += __shfl_xor_sync(0xffffffffu, s0, o);
        s1 += __shfl_xor_sync(0xffffffffu, s1, o);
        s2 += __shfl_xor_sync(0xffffffffu, s2, o);
    }
    s0 *= 4096.0f; s1 *= 4096.0f; s2 *= 4096.0f;
    float m = fmaxf(s0, fmaxf(s1, s2));
    float e0 = expf(s0 - m), e1 = expf(s1 - m), e2 = expf(s2 - m);
    float inv = 1.0f / (e0 + e1 + e2);
    e0 *= inv; e1 *= inv; e2 *= inv;

    const float* v0p = k0p + E_DIM;
    const float* v1p = k1p + E_DIM;
    const float* v2p = k2p + E_DIM;
    float o0 = e0 * v0p[d0] + e1 * v1p[d0] + e2 * v2p[d0];
    float o1 = e0 * v0p[d0 + 1] + e1 * v1p[d0 + 1] + e2 * v2p[d0 + 1];

    float g = gate[h];
    size_t off = (size_t)t * E_DIM + h * 64 + d0;
    g_comb[off]     = o0 * g + y[off] * (1.0f - g);
    g_comb[off + 1] = o1 * g + y[off + 1] * (1.0f - g);
}

// ---------------- launch ----------------
extern "C" void kernel_launch(void* const* d_in, const int* in_sizes, int n_in,
                              void* d_out, int out_size) {
    const float* x = nullptr;
    const float* mem_db = nullptr;
    const float* W_attn = nullptr;
    const float* W_proj = nullptr;
    const float* gate = nullptr;
    for (int i = 0; i < n_in; i++) {
        switch (in_sizes[i]) {
            case 2048 * 1024:       x      = (const float*)d_in[i]; break;
            case 32768 * 2048:      mem_db = (const float*)d_in[i]; break;
            case 3072 * 1024:       W_attn = (const float*)d_in[i]; break;
            case 1024 * 1024:       W_proj = (const float*)d_in[i]; break;
            case 16:                gate   = (const float*)d_in[i]; break;
            default: break;
        }
    }
    float* out = (float*)d_out;

    void *p_qkv, *p_y, *p_S, *p_comb, *p_mkn, *p_qbf, *p_mkbf;
    cudaGetSymbolAddress(&p_qkv, g_qkv);
    cudaGetSymbolAddress(&p_y, g_y);
    cudaGetSymbolAddress(&p_S, g_S);
    cudaGetSymbolAddress(&p_comb, g_comb);
    cudaGetSymbolAddress(&p_mkn, g_mknorm);
    cudaGetSymbolAddress(&p_qbf, g_qbf);
    cudaGetSymbolAddress(&p_mkbf, g_mkbf);
    float* qkv = (float*)p_qkv;
    float* y = (float*)p_y;
    float* S = (float*)p_S;
    float* comb = (float*)p_comb;
    float* mkn = (float*)p_mkn;
    __nv_bfloat16* qbf = (__nv_bfloat16*)p_qbf;
    __nv_bfloat16* mkbf = (__nv_bfloat16*)p_mkbf;

    const int FLASH_SMEM = (4 * 64 * 68 + 64 * 3 + 256) * 4;
    cudaFuncSetAttribute(flash_tf32_kernel,
                         cudaFuncAttributeMaxDynamicSharedMemorySize, FLASH_SMEM);

    // 1a) q = x @ W_attn[0:1024]^T  (fp32 — ranking-exact path)
    sgemm_nt<<<dim3(1024 / 128, 2048 / 128), 256>>>(
        x, E_DIM, W_attn, E_DIM, qkv, 3 * E_DIM, E_DIM);
    // 1b) k,v = x @ W_attn[1024:3072]^T  (tf32 tensor cores — smooth path)
    gemm_tf32_nt<<<dim3(2048 / 128, 2048 / 128), 256>>>(
        x, E_DIM, W_attn + (size_t)E_DIM * E_DIM, E_DIM,
        qkv + E_DIM, 3 * E_DIM, E_DIM);

    // 2) |mem_key|^2 and bf16 conversions
    mknorm_kernel<<<M_DIM / 8, 256>>>(mem_db);
    cvt_mk_kernel<<<M_DIM, 256>>>(mem_db, mkbf);
    cvt_q_kernel<<<T_DIM, 256>>>(qkv, qbf);

    // 3) causal attention -> y [T, E]  (tf32 tensor cores)
    flash_tf32_kernel<<<dim3(T_DIM / 64, H_DIM), 256, FLASH_SMEM>>>(qkv, y);

    // 4) coarse S = -2 q @ mem_keys^T + |mk|^2  (bf16 tensor cores)
    gemm_bf16_nt<<<dim3(M_DIM / 128, T_DIM / 128), 256>>>(qbf, mkbf, S, mkn);

    // 5) coarse top-8 candidates, then exact fp32 rescore -> top-3
    top8_kernel<<<T_DIM, 256>>>(S);
    rescore_kernel<<<T_DIM, 256>>>(qkv, mem_db, mkn);

    // 6) mem attention + gated combine -> comb [T, E]
    memattn_kernel<<<T_DIM, 512>>>(qkv, mem_db, y, gate);

    // 7) out = comb @ W_proj^T  (tf32 tensor cores)
    gemm_tf32_nt<<<dim3(1024 / 128, 2048 / 128), 256>>>(
        comb, E_DIM, W_proj, E_DIM, out, E_DIM, E_DIM);
}